// round 13
// baseline (speedup 1.0000x reference)
#include <cuda_runtime.h>
#include <cuda_fp16.h>
#include <cstdint>
#include <math.h>

// CBTree B=4, L=9, d=256.
// Split-fp16 2-term: A=[hi(u)|lo(u)] fp16 (K=1024), B=hi(W) fp16 (K=512).
// 16 chunk passes of 64 (it 0-7 hi, 8-15 lo; b = it&7).
// l=7: full-K fused GEMM (tanh+combine -> Anext). l=6,5: split-K + epilogue.
// l=4..0: fp32 SIMT warp-per-output (l=5 epilogue emits fp32 h).

#define D 256
#define KA 1024
#define ROWA 2048        // A row bytes (1024 fp16)
#define ROWBB 1024       // B row bytes (512 fp16)
#define NCHUNK 16
#define SROW 144
#define TILE_B (128 * SROW)
#define STAGE (2 * TILE_B)            // 36864
#define NSTAGE 3
#define SMEM_TOTAL (NSTAGE * STAGE)   // 110592 (2 CTAs/SM)
#define HST 132
#define NTHR 512

// ---------------- static device scratch ----------------
__device__ __half g_Acat0[16384 * 1024];
__device__ __half g_Acat1[16384 * 1024];
__device__ __half g_Bcat[256 * 512];
__device__ float g_part[16384 * 256];
__device__ float g_hs5[1024 * 256];    // fp32 h at level 5
__device__ float g_hsA[256 * 256];
__device__ float g_hsB[256 * 256];

// ---------------- helpers ----------------
__device__ __forceinline__ uint32_t smem_u32(const void* p) {
    uint32_t a;
    asm("{ .reg .u64 t; cvta.to.shared.u64 t, %1; cvt.u32.u64 %0, t; }" : "=r"(a) : "l"(p));
    return a;
}
__device__ __forceinline__ void cp_async16(uint32_t dst, const void* src) {
    asm volatile("cp.async.cg.shared.global [%0], [%1], 16;" :: "r"(dst), "l"(src));
}
#define CP_COMMIT() asm volatile("cp.async.commit_group;" ::: "memory")

__device__ __forceinline__ void ldm_x4(uint32_t* r, uint32_t addr) {
    asm volatile("ldmatrix.sync.aligned.m8n8.x4.shared.b16 {%0,%1,%2,%3}, [%4];"
                 : "=r"(r[0]), "=r"(r[1]), "=r"(r[2]), "=r"(r[3]) : "r"(addr));
}
__device__ __forceinline__ void mma_f16(float* c, const uint32_t* a, uint32_t b0, uint32_t b1) {
    asm volatile("mma.sync.aligned.m16n8k16.row.col.f32.f16.f16.f32 "
                 "{%0,%1,%2,%3}, {%4,%5,%6,%7}, {%8,%9}, {%0,%1,%2,%3};"
                 : "+f"(c[0]), "+f"(c[1]), "+f"(c[2]), "+f"(c[3])
                 : "r"(a[0]), "r"(a[1]), "r"(a[2]), "r"(a[3]), "r"(b0), "r"(b1));
}
__device__ __forceinline__ void split_fp16(float v, __half& hi, __half& lo) {
    hi = __float2half_rn(v);
    lo = __float2half_rn(v - __half2float(hi));
}

// Per-chunk compute for 32x32 warp tile: 4 ldm_x4 + 8 MMA per kk.
__device__ __forceinline__ void compute_chunk(uint32_t aAddr, uint32_t bAddr,
                                              float acc[2][4][4]) {
#pragma unroll
    for (int kk = 0; kk < 4; kk++) {
        uint32_t a0[4], a1[4], b0[4], b1[4];
        ldm_x4(a0, aAddr + kk * 32);
        ldm_x4(a1, aAddr + 16 * SROW + kk * 32);
        ldm_x4(b0, bAddr + kk * 32);
        ldm_x4(b1, bAddr + 16 * SROW + kk * 32);
        mma_f16(acc[0][0], a0, b0[0], b0[1]);
        mma_f16(acc[0][1], a0, b0[2], b0[3]);
        mma_f16(acc[0][2], a0, b1[0], b1[1]);
        mma_f16(acc[0][3], a0, b1[2], b1[3]);
        mma_f16(acc[1][0], a1, b0[0], b0[1]);
        mma_f16(acc[1][1], a1, b0[2], b0[3]);
        mma_f16(acc[1][2], a1, b1[0], b1[1]);
        mma_f16(acc[1][3], a1, b1[2], b1[3]);
    }
}

// ---------------- prep: Bcat = hi(W) fp16 ----------------
__global__ void prep_w_kernel(const float* __restrict__ Wl,
                              const float* __restrict__ Wr,
                              __half* __restrict__ Bcat) {
    int idx = blockIdx.x * blockDim.x + threadIdx.x;
    if (idx >= D * 512) return;
    int n = idx >> 9;
    int k = idx & 511;
    float w = (k < D) ? Wl[n * D + k] : Wr[n * D + (k - D)];
    Bcat[(size_t)n * 512 + k] = __float2half_rn(w);
}

// ---------------- leaf reduce -> Acat [hiL|hiR|loL|loR] fp16 ----------------
// One thread per (parent, col-quad): computes BOTH uL and uR, sharing the
// b,c child loads (64 MB total read instead of 96 MB; MLP=4).
__global__ void __launch_bounds__(256)
leaf_reduce_kernel(const float* __restrict__ h,
                   __half* __restrict__ Acat,
                   int n_par) {
    int idx = blockIdx.x * blockDim.x + threadIdx.x;   // n_par * 64
    if (idx >= n_par * 64) return;
    int p = idx >> 6;
    int q = idx & 63;                                  // float4 index within 256 cols
    const float4* hp = (const float4*)(h + (size_t)p * 1024);
    float4 a = hp[q];
    float4 b = hp[64 + q];
    float4 c = hp[128 + q];
    float4 d = hp[192 + q];

    float uL[4], uR[4];
    uL[0] = a.x + (2.f/3.f) * b.x + (1.f/3.f) * c.x;
    uL[1] = a.y + (2.f/3.f) * b.y + (1.f/3.f) * c.y;
    uL[2] = a.z + (2.f/3.f) * b.z + (1.f/3.f) * c.z;
    uL[3] = a.w + (2.f/3.f) * b.w + (1.f/3.f) * c.w;
    uR[0] = (1.f/3.f) * b.x + (2.f/3.f) * c.x + d.x;
    uR[1] = (1.f/3.f) * b.y + (2.f/3.f) * c.y + d.y;
    uR[2] = (1.f/3.f) * b.z + (2.f/3.f) * c.z + d.z;
    uR[3] = (1.f/3.f) * b.w + (2.f/3.f) * c.w + d.w;

    __half lh[4], ll[4], rh[4], rl[4];
#pragma unroll
    for (int j = 0; j < 4; j++) {
        split_fp16(uL[j], lh[j], ll[j]);
        split_fp16(uR[j], rh[j], rl[j]);
    }
    __half* arow = Acat + (size_t)p * KA + q * 4;
    *(uint2*)(arow)       = *(const uint2*)lh;   // hi, k in [0,256)
    *(uint2*)(arow + 256) = *(const uint2*)rh;   // hi, k in [256,512)
    *(uint2*)(arow + 512) = *(const uint2*)ll;   // lo, k in [0,256)
    *(uint2*)(arow + 768) = *(const uint2*)rl;   // lo, k in [256,512)
}

// ======== stage loader (512 threads) ========
__device__ __forceinline__ void load_stage_g(uint32_t sbase, int slot, int it,
                                             const char* Ab, const char* Bb, int tid) {
    int aCh = it;
    int bCh = it & 7;
    uint32_t sA = sbase + slot * STAGE;
    uint32_t sB = sA + TILE_B;
#pragma unroll
    for (int i = 0; i < 2; i++) {
        int id = i * NTHR + tid;
        int r = id >> 3, c = id & 7;
        cp_async16(sA + r * SROW + c * 16, Ab + (size_t)r * ROWA + aCh * 128 + c * 16);
    }
#pragma unroll
    for (int i = 0; i < 2; i++) {
        int id = i * NTHR + tid;
        int r = id >> 3, c = id & 7;
        cp_async16(sB + r * SROW + c * 16, Bb + (size_t)r * ROWBB + bCh * 128 + c * 16);
    }
    CP_COMMIT();
}

// ---------------- l=7: full-K GEMM + fused tanh/combine epilogue ----------------
__global__ void __launch_bounds__(NTHR, 2)
gemm_fused_l7(const __half* __restrict__ A,
              const __half* __restrict__ B,
              const float* __restrict__ bias,
              __half* __restrict__ Anext, int M) {
    extern __shared__ __align__(128) char smem[];
    const uint32_t sbase = smem_u32(smem);
    const int tid = threadIdx.x;
    const int wid = tid >> 5;
    const int lid = tid & 31;
    const int bn = blockIdx.x * 128;
    const int bm = blockIdx.y * 128;

    const char* Ab = (const char*)A + (size_t)bm * ROWA;
    const char* Bb = (const char*)B + (size_t)bn * ROWBB;

    float acc[2][4][4];
#pragma unroll
    for (int mf = 0; mf < 2; mf++)
#pragma unroll
        for (int nf = 0; nf < 4; nf++)
#pragma unroll
            for (int q = 0; q < 4; q++) acc[mf][nf][q] = 0.0f;

    const int wm = (wid & 3) * 32;
    const int wn = (wid >> 2) * 32;
    const uint32_t aOff = (uint32_t)(wm + (lid & 7) + ((lid & 8) ? 8 : 0)) * SROW +
                          ((lid & 16) ? 16 : 0);
    const uint32_t bOff = (uint32_t)(wn + (lid & 7) + ((lid & 16) ? 8 : 0)) * SROW +
                          ((lid & 8) ? 16 : 0);

    load_stage_g(sbase, 0, 0, Ab, Bb, tid);
    load_stage_g(sbase, 1, 1, Ab, Bb, tid);

    for (int it = 0; it < NCHUNK; it++) {
        if (it + 2 < NCHUNK) {
            asm volatile("cp.async.wait_group 1;" ::: "memory");
        } else {
            asm volatile("cp.async.wait_group 0;" ::: "memory");
        }
        __syncthreads();
        if (it + 2 < NCHUNK)
            load_stage_g(sbase, (it + 2) % NSTAGE, it + 2, Ab, Bb, tid);

        uint32_t sA = sbase + (it % NSTAGE) * STAGE;
        compute_chunk(sA + aOff, sA + TILE_B + bOff, acc);
    }
    __syncthreads();

    // epilogue: tanh(acc+bias) -> smem h tile
    float* hs = (float*)smem;
#pragma unroll
    for (int mf = 0; mf < 2; mf++) {
#pragma unroll
        for (int half = 0; half < 2; half++) {
            int r = wm + mf * 16 + (lid >> 2) + half * 8;
            const float* brow = bias + (size_t)(bm + r) * D + bn + wn;
            float* hrow = hs + r * HST + wn;
#pragma unroll
            for (int nf = 0; nf < 4; nf++) {
                int col = nf * 8 + 2 * (lid & 3);
                float2 bv = *(const float2*)(brow + col);
                hrow[col] = tanhf(acc[mf][nf][half * 2 + 0] + bv.x);
                hrow[col + 1] = tanhf(acc[mf][nf][half * 2 + 1] + bv.y);
            }
        }
    }
    __syncthreads();

    // fused child-combine -> Anext columns [bn, bn+128): 512 thr, 8 cols each
    {
        int p = tid >> 4;          // 0..31
        int g = tid & 15;          // 0..15 -> 8-col group
        int pg = (bm >> 2) + p;
        const float* h0 = hs + (4 * p + 0) * HST;
        const float* h1 = hs + (4 * p + 1) * HST;
        const float* h2 = hs + (4 * p + 2) * HST;
        const float* h3 = hs + (4 * p + 3) * HST;
        __half* arow = Anext + (size_t)pg * KA;
        int c0 = g * 8;
        __half lh[8], ll[8], rh[8], rl[8];
#pragma unroll
        for (int j = 0; j < 8; j++) {
            float a = h0[c0 + j], b = h1[c0 + j], c = h2[c0 + j], d = h3[c0 + j];
            float lv = a + (2.f/3.f) * b + (1.f/3.f) * c;
            float rv = (1.f/3.f) * b + (2.f/3.f) * c + d;
            split_fp16(lv, lh[j], ll[j]);
            split_fp16(rv, rh[j], rl[j]);
        }
        int cL = bn + c0;
        *(uint4*)(arow + cL) = *(const uint4*)lh;
        *(uint4*)(arow + 512 + cL) = *(const uint4*)ll;
        *(uint4*)(arow + 256 + cL) = *(const uint4*)rh;
        *(uint4*)(arow + 768 + cL) = *(const uint4*)rl;
    }
}

// ---------------- split-K partial GEMM (l=6,5) ----------------
__global__ void __launch_bounds__(NTHR, 2)
gemm_partial_kernel(const __half* __restrict__ A,
                    const __half* __restrict__ B,
                    float* __restrict__ P, int M, int cnt) {
    extern __shared__ __align__(128) char smem[];
    const uint32_t sbase = smem_u32(smem);
    const int tid = threadIdx.x;
    const int wid = tid >> 5;
    const int lid = tid & 31;
    const int bn = blockIdx.x * 128;
    const int bm = blockIdx.y * 128;
    const int c0 = blockIdx.z * cnt;

    const char* Ab = (const char*)A + (size_t)bm * ROWA;
    const char* Bb = (const char*)B + (size_t)bn * ROWBB;
    float* Pb = P + ((size_t)blockIdx.z * M + bm) * D + bn;

    float acc[2][4][4];
#pragma unroll
    for (int mf = 0; mf < 2; mf++)
#pragma unroll
        for (int nf = 0; nf < 4; nf++)
#pragma unroll
            for (int q = 0; q < 4; q++) acc[mf][nf][q] = 0.0f;

    const int wm = (wid & 3) * 32;
    const int wn = (wid >> 2) * 32;
    const uint32_t aOff = (uint32_t)(wm + (lid & 7) + ((lid & 8) ? 8 : 0)) * SROW +
                          ((lid & 16) ? 16 : 0);
    const uint32_t bOff = (uint32_t)(wn + (lid & 7) + ((lid & 16) ? 8 : 0)) * SROW +
                          ((lid & 8) ? 16 : 0);

    load_stage_g(sbase, 0, c0, Ab, Bb, tid);
    if (cnt > 1) load_stage_g(sbase, 1, c0 + 1, Ab, Bb, tid);

    for (int i = 0; i < cnt; i++) {
        if (i + 2 < cnt) {
            asm volatile("cp.async.wait_group 1;" ::: "memory");
        } else {
            asm volatile("cp.async.wait_group 0;" ::: "memory");
        }
        __syncthreads();
        if (i + 2 < cnt)
            load_stage_g(sbase, (i + 2) % NSTAGE, c0 + i + 2, Ab, Bb, tid);

        uint32_t sA = sbase + (i % NSTAGE) * STAGE;
        compute_chunk(sA + aOff, sA + TILE_B + bOff, acc);
    }

#pragma unroll
    for (int mf = 0; mf < 2; mf++) {
#pragma unroll
        for (int half = 0; half < 2; half++) {
            int r = wm + mf * 16 + (lid >> 2) + half * 8;
            float* prow = Pb + (size_t)r * D + wn;
#pragma unroll
            for (int nf = 0; nf < 4; nf++) {
                int col = nf * 8 + 2 * (lid & 3);
                float2 o;
                o.x = acc[mf][nf][half * 2 + 0];
                o.y = acc[mf][nf][half * 2 + 1];
                *(float2*)(prow + col) = o;
            }
        }
    }
}

// ---------------- epilogue: sum splits + bias + tanh + combine + split ----------------
__global__ void __launch_bounds__(256)
epilogue_combine_kernel(const float* __restrict__ P, int S,
                        const float* __restrict__ bias,
                        __half* __restrict__ Anext,
                        float* __restrict__ hout, int M) {
    int idx = blockIdx.x * blockDim.x + threadIdx.x;
    int nPar = M >> 2;
    if (idx >= nPar * 64) return;
    int p = idx >> 6;
    int q = idx & 63;

    float4 h[4];
#pragma unroll
    for (int j = 0; j < 4; j++) {
        int row = 4 * p + j;
        float4 sum = *(const float4*)(P + (size_t)row * D + q * 4);
        for (int s = 1; s < S; s++) {
            float4 t = *(const float4*)(P + ((size_t)s * M + row) * D + q * 4);
            sum.x += t.x; sum.y += t.y; sum.z += t.z; sum.w += t.w;
        }
        float4 bv = *(const float4*)(bias + (size_t)row * D + q * 4);
        h[j].x = tanhf(sum.x + bv.x);
        h[j].y = tanhf(sum.y + bv.y);
        h[j].z = tanhf(sum.z + bv.z);
        h[j].w = tanhf(sum.w + bv.w);
        if (hout) *(float4*)(hout + (size_t)row * D + q * 4) = h[j];
    }

    if (Anext) {
        float4 uL, uR;
        uL.x = h[0].x + (2.f/3.f) * h[1].x + (1.f/3.f) * h[2].x;
        uL.y = h[0].y + (2.f/3.f) * h[1].y + (1.f/3.f) * h[2].y;
        uL.z = h[0].z + (2.f/3.f) * h[1].z + (1.f/3.f) * h[2].z;
        uL.w = h[0].w + (2.f/3.f) * h[1].w + (1.f/3.f) * h[2].w;
        uR.x = (1.f/3.f) * h[1].x + (2.f/3.f) * h[2].x + h[3].x;
        uR.y = (1.f/3.f) * h[1].y + (2.f/3.f) * h[2].y + h[3].y;
        uR.z = (1.f/3.f) * h[1].z + (2.f/3.f) * h[2].z + h[3].z;
        uR.w = (1.f/3.f) * h[1].w + (2.f/3.f) * h[2].w + h[3].w;

        __half lh[4], ll[4], rh[4], rl[4];
        split_fp16(uL.x, lh[0], ll[0]);
        split_fp16(uL.y, lh[1], ll[1]);
        split_fp16(uL.z, lh[2], ll[2]);
        split_fp16(uL.w, lh[3], ll[3]);
        split_fp16(uR.x, rh[0], rl[0]);
        split_fp16(uR.y, rh[1], rl[1]);
        split_fp16(uR.z, rh[2], rl[2]);
        split_fp16(uR.w, rh[3], rl[3]);

        __half* arow = Anext + (size_t)p * KA + q * 4;
        *(uint2*)(arow)       = *(const uint2*)lh;
        *(uint2*)(arow + 256) = *(const uint2*)rh;
        *(uint2*)(arow + 512) = *(const uint2*)ll;
        *(uint2*)(arow + 768) = *(const uint2*)rl;
    }
}

// ---------------- small levels (M<=256): fp32 warp-per-output ----------------
__global__ void __launch_bounds__(256)
small_level_kernel(const float* __restrict__ hprev,
                   const float* __restrict__ Wl,
                   const float* __restrict__ Wr,
                   const float* __restrict__ bias,
                   float* __restrict__ hout, int Mout) {
    int gw = (blockIdx.x * blockDim.x + threadIdx.x) >> 5;
    int lid = threadIdx.x & 31;
    if (gw >= Mout * D) return;
    int p = gw >> 8;
    int n = gw & 255;
    const float* h0 = hprev + (size_t)(4 * p) * D;
    const float* wl = Wl + (size_t)n * D;
    const float* wr = Wr + (size_t)n * D;
    float acc = 0.f;
#pragma unroll
    for (int i = 0; i < 8; i++) {
        int k = lid + i * 32;
        float a = h0[k], b = h0[D + k], c = h0[2 * D + k], d = h0[3 * D + k];
        float uL = a + (2.f/3.f) * b + (1.f/3.f) * c;
        float uR = (1.f/3.f) * b + (2.f/3.f) * c + d;
        acc = fmaf(uL, wl[k], acc);
        acc = fmaf(uR, wr[k], acc);
    }
#pragma unroll
    for (int o = 16; o; o >>= 1) acc += __shfl_xor_sync(0xffffffffu, acc, o);
    if (lid == 0)
        hout[(size_t)p * D + n] = tanhf(acc + bias[(size_t)p * D + n]);
}

// ---------------- launcher ----------------
extern "C" void kernel_launch(void* const* d_in, const int* in_sizes, int n_in,
                              void* d_out, int out_size) {
    const float* vectors = (const float*)d_in[0];
    const float* Wl = (const float*)d_in[1];
    const float* Wr = (const float*)d_in[2];
    float* out = (float*)d_out;

    __half *Acat0, *Acat1, *Bcat;
    float *part, *hs5, *hsA, *hsB;
    cudaGetSymbolAddress((void**)&Acat0, g_Acat0);
    cudaGetSymbolAddress((void**)&Acat1, g_Acat1);
    cudaGetSymbolAddress((void**)&Bcat, g_Bcat);
    cudaGetSymbolAddress((void**)&part, g_part);
    cudaGetSymbolAddress((void**)&hs5, g_hs5);
    cudaGetSymbolAddress((void**)&hsA, g_hsA);
    cudaGetSymbolAddress((void**)&hsB, g_hsB);

    cudaFuncSetAttribute(gemm_fused_l7,
                         cudaFuncAttributeMaxDynamicSharedMemorySize, SMEM_TOTAL);
    cudaFuncSetAttribute(gemm_fused_l7,
                         cudaFuncAttributePreferredSharedMemoryCarveout, 100);
    cudaFuncSetAttribute(gemm_partial_kernel,
                         cudaFuncAttributeMaxDynamicSharedMemorySize, SMEM_TOTAL);
    cudaFuncSetAttribute(gemm_partial_kernel,
                         cudaFuncAttributePreferredSharedMemoryCarveout, 100);

    prep_w_kernel<<<(D * 512 + 255) / 256, 256>>>(Wl, Wr, Bcat);

    static const int offs[9] = {0, 1, 5, 21, 85, 341, 1365, 5461, 21845};

    const float* leaves = vectors + (size_t)offs[8] * D;
    leaf_reduce_kernel<<<(16384 * 64 + 255) / 256, 256>>>(leaves, Acat0, 16384);

    // l=7: fused full-K GEMM, Acat0 -> Acat1
    {
        dim3 grid(2, 128);
        gemm_fused_l7<<<grid, NTHR, SMEM_TOTAL>>>(
            Acat0, Bcat, vectors + (size_t)offs[7] * D, Acat1, 16384);
    }

    // l=6: split-K S=4 (cnt=4), Acat1 -> Acat0
    {
        int M = 4096, S = 4, cnt = NCHUNK / S;
        dim3 grid(2, M / 128, S);
        gemm_partial_kernel<<<grid, NTHR, SMEM_TOTAL>>>(Acat1, Bcat, part, M, cnt);
        int nthr = (M / 4) * 64;
        epilogue_combine_kernel<<<(nthr + 255) / 256, 256>>>(
            part, S, vectors + (size_t)offs[6] * D, Acat0, nullptr, M);
    }

    // l=5: split-K S=8 (cnt=2), Acat0 -> fp32 h (g_hs5), no Anext
    {
        int M = 1024, S = 8, cnt = NCHUNK / S;
        dim3 grid(2, M / 128, S);
        gemm_partial_kernel<<<grid, NTHR, SMEM_TOTAL>>>(Acat0, Bcat, part, M, cnt);
        int nthr = (M / 4) * 64;
        epilogue_combine_kernel<<<(nthr + 255) / 256, 256>>>(
            part, S, vectors + (size_t)offs[5] * D, nullptr, hs5, M);
    }

    // l=4..0: fp32 SIMT. hs5 -> hsA -> hsB -> hsA -> hsB -> out
    const float* hin = hs5;
    for (int l = 4; l >= 0; --l) {
        int M = 1 << (2 * l);
        float* hout;
        if (l == 0) hout = out;
        else hout = (l & 1) ? hsB : hsA;   // l=4->hsA? (4&1)=0 -> hsA ✓, l=3->hsB, ...
        const float* bias = vectors + (size_t)offs[l] * D;
        int nwarps = M * D;
        small_level_kernel<<<(nwarps * 32 + 255) / 256, 256>>>(hin, Wl, Wr, bias, hout, M);
        hin = hout;
    }
}

// round 14
// speedup vs baseline: 1.1798x; 1.1798x over previous
#include <cuda_runtime.h>
#include <cuda_fp16.h>
#include <cstdint>
#include <math.h>

// CBTree B=4, L=9, d=256.
// A=[hi(u)|lo(u)] fp16 (K=1024), B=hi(W) fp16 (K=512).
// l=7: 1-term (hi only, 8 chunks) fused GEMM (tanh+combine -> Anext).
// l=6,5,4: 2-term (16 chunks) split-K + epilogue. l=3..0: fp32 SIMT.

#define D 256
#define KA 1024
#define ROWA 2048        // A row bytes (1024 fp16)
#define ROWBB 1024       // B row bytes (512 fp16)
#define NCHUNK 16
#define SROW 144
#define TILE_B (128 * SROW)
#define STAGE (2 * TILE_B)            // 36864
#define NSTAGE 3
#define SMEM_TOTAL (NSTAGE * STAGE)   // 110592 (2 CTAs/SM)
#define HST 132
#define NTHR 512

// ---------------- static device scratch ----------------
__device__ __half g_Acat0[16384 * 1024];
__device__ __half g_Acat1[16384 * 1024];
__device__ __half g_Bcat[256 * 512];
__device__ float g_part[16384 * 256];
__device__ float g_hsA[256 * 256];
__device__ float g_hsB[256 * 256];

// ---------------- helpers ----------------
__device__ __forceinline__ uint32_t smem_u32(const void* p) {
    uint32_t a;
    asm("{ .reg .u64 t; cvta.to.shared.u64 t, %1; cvt.u32.u64 %0, t; }" : "=r"(a) : "l"(p));
    return a;
}
__device__ __forceinline__ void cp_async16(uint32_t dst, const void* src) {
    asm volatile("cp.async.cg.shared.global [%0], [%1], 16;" :: "r"(dst), "l"(src));
}
#define CP_COMMIT() asm volatile("cp.async.commit_group;" ::: "memory")

__device__ __forceinline__ void ldm_x4(uint32_t* r, uint32_t addr) {
    asm volatile("ldmatrix.sync.aligned.m8n8.x4.shared.b16 {%0,%1,%2,%3}, [%4];"
                 : "=r"(r[0]), "=r"(r[1]), "=r"(r[2]), "=r"(r[3]) : "r"(addr));
}
__device__ __forceinline__ void mma_f16(float* c, const uint32_t* a, uint32_t b0, uint32_t b1) {
    asm volatile("mma.sync.aligned.m16n8k16.row.col.f32.f16.f16.f32 "
                 "{%0,%1,%2,%3}, {%4,%5,%6,%7}, {%8,%9}, {%0,%1,%2,%3};"
                 : "+f"(c[0]), "+f"(c[1]), "+f"(c[2]), "+f"(c[3])
                 : "r"(a[0]), "r"(a[1]), "r"(a[2]), "r"(a[3]), "r"(b0), "r"(b1));
}
__device__ __forceinline__ void split_fp16(float v, __half& hi, __half& lo) {
    hi = __float2half_rn(v);
    lo = __float2half_rn(v - __half2float(hi));
}

// Per-chunk compute for 32x32 warp tile: 4 ldm_x4 + 8 MMA per kk.
__device__ __forceinline__ void compute_chunk(uint32_t aAddr, uint32_t bAddr,
                                              float acc[2][4][4]) {
#pragma unroll
    for (int kk = 0; kk < 4; kk++) {
        uint32_t a0[4], a1[4], b0[4], b1[4];
        ldm_x4(a0, aAddr + kk * 32);
        ldm_x4(a1, aAddr + 16 * SROW + kk * 32);
        ldm_x4(b0, bAddr + kk * 32);
        ldm_x4(b1, bAddr + 16 * SROW + kk * 32);
        mma_f16(acc[0][0], a0, b0[0], b0[1]);
        mma_f16(acc[0][1], a0, b0[2], b0[3]);
        mma_f16(acc[0][2], a0, b1[0], b1[1]);
        mma_f16(acc[0][3], a0, b1[2], b1[3]);
        mma_f16(acc[1][0], a1, b0[0], b0[1]);
        mma_f16(acc[1][1], a1, b0[2], b0[3]);
        mma_f16(acc[1][2], a1, b1[0], b1[1]);
        mma_f16(acc[1][3], a1, b1[2], b1[3]);
    }
}

// ---------------- prep: Bcat = hi(W) fp16 ----------------
__global__ void prep_w_kernel(const float* __restrict__ Wl,
                              const float* __restrict__ Wr,
                              __half* __restrict__ Bcat) {
    int idx = blockIdx.x * blockDim.x + threadIdx.x;
    if (idx >= D * 512) return;
    int n = idx >> 9;
    int k = idx & 511;
    float w = (k < D) ? Wl[n * D + k] : Wr[n * D + (k - D)];
    Bcat[(size_t)n * 512 + k] = __float2half_rn(w);
}

// ---------------- leaf reduce -> Acat hi halves only (l=7 is 1-term) ----------------
__global__ void __launch_bounds__(256)
leaf_reduce_kernel(const float* __restrict__ h,
                   __half* __restrict__ Acat,
                   int n_par) {
    int idx = blockIdx.x * blockDim.x + threadIdx.x;   // n_par * 64
    if (idx >= n_par * 64) return;
    int p = idx >> 6;
    int q = idx & 63;
    const float4* hp = (const float4*)(h + (size_t)p * 1024);
    float4 a = hp[q];
    float4 b = hp[64 + q];
    float4 c = hp[128 + q];
    float4 d = hp[192 + q];

    __half lh[4], rh[4];
    lh[0] = __float2half_rn(a.x + (2.f/3.f) * b.x + (1.f/3.f) * c.x);
    lh[1] = __float2half_rn(a.y + (2.f/3.f) * b.y + (1.f/3.f) * c.y);
    lh[2] = __float2half_rn(a.z + (2.f/3.f) * b.z + (1.f/3.f) * c.z);
    lh[3] = __float2half_rn(a.w + (2.f/3.f) * b.w + (1.f/3.f) * c.w);
    rh[0] = __float2half_rn((1.f/3.f) * b.x + (2.f/3.f) * c.x + d.x);
    rh[1] = __float2half_rn((1.f/3.f) * b.y + (2.f/3.f) * c.y + d.y);
    rh[2] = __float2half_rn((1.f/3.f) * b.z + (2.f/3.f) * c.z + d.z);
    rh[3] = __float2half_rn((1.f/3.f) * b.w + (2.f/3.f) * c.w + d.w);

    __half* arow = Acat + (size_t)p * KA + q * 4;
    *(uint2*)(arow)       = *(const uint2*)lh;   // hi, k in [0,256)
    *(uint2*)(arow + 256) = *(const uint2*)rh;   // hi, k in [256,512)
}

// ======== stage loader (512 threads): aCh=it, bCh=it&7 (works for 8 or 16 chunks) ========
__device__ __forceinline__ void load_stage_g(uint32_t sbase, int slot, int it,
                                             const char* Ab, const char* Bb, int tid) {
    int aCh = it;
    int bCh = it & 7;
    uint32_t sA = sbase + slot * STAGE;
    uint32_t sB = sA + TILE_B;
#pragma unroll
    for (int i = 0; i < 2; i++) {
        int id = i * NTHR + tid;
        int r = id >> 3, c = id & 7;
        cp_async16(sA + r * SROW + c * 16, Ab + (size_t)r * ROWA + aCh * 128 + c * 16);
    }
#pragma unroll
    for (int i = 0; i < 2; i++) {
        int id = i * NTHR + tid;
        int r = id >> 3, c = id & 7;
        cp_async16(sB + r * SROW + c * 16, Bb + (size_t)r * ROWBB + bCh * 128 + c * 16);
    }
    CP_COMMIT();
}

// ---------------- l=7: 1-term GEMM (8 chunks) + fused tanh/combine epilogue ----------------
__global__ void __launch_bounds__(NTHR, 2)
gemm_fused_l7(const __half* __restrict__ A,
              const __half* __restrict__ B,
              const float* __restrict__ bias,
              __half* __restrict__ Anext, int M) {
    extern __shared__ __align__(128) char smem[];
    const uint32_t sbase = smem_u32(smem);
    const int tid = threadIdx.x;
    const int wid = tid >> 5;
    const int lid = tid & 31;
    const int bn = blockIdx.x * 128;
    const int bm = blockIdx.y * 128;

    const char* Ab = (const char*)A + (size_t)bm * ROWA;
    const char* Bb = (const char*)B + (size_t)bn * ROWBB;

    float acc[2][4][4];
#pragma unroll
    for (int mf = 0; mf < 2; mf++)
#pragma unroll
        for (int nf = 0; nf < 4; nf++)
#pragma unroll
            for (int q = 0; q < 4; q++) acc[mf][nf][q] = 0.0f;

    const int wm = (wid & 3) * 32;
    const int wn = (wid >> 2) * 32;
    const uint32_t aOff = (uint32_t)(wm + (lid & 7) + ((lid & 8) ? 8 : 0)) * SROW +
                          ((lid & 16) ? 16 : 0);
    const uint32_t bOff = (uint32_t)(wn + (lid & 7) + ((lid & 16) ? 8 : 0)) * SROW +
                          ((lid & 8) ? 16 : 0);

    const int NCH = 8;   // 1-term: hi chunks only
    load_stage_g(sbase, 0, 0, Ab, Bb, tid);
    load_stage_g(sbase, 1, 1, Ab, Bb, tid);

    for (int it = 0; it < NCH; it++) {
        if (it + 2 < NCH) {
            asm volatile("cp.async.wait_group 1;" ::: "memory");
        } else {
            asm volatile("cp.async.wait_group 0;" ::: "memory");
        }
        __syncthreads();
        if (it + 2 < NCH)
            load_stage_g(sbase, (it + 2) % NSTAGE, it + 2, Ab, Bb, tid);

        uint32_t sA = sbase + (it % NSTAGE) * STAGE;
        compute_chunk(sA + aOff, sA + TILE_B + bOff, acc);
    }
    __syncthreads();

    // epilogue: tanh(acc+bias) -> smem h tile
    float* hs = (float*)smem;
#pragma unroll
    for (int mf = 0; mf < 2; mf++) {
#pragma unroll
        for (int half = 0; half < 2; half++) {
            int r = wm + mf * 16 + (lid >> 2) + half * 8;
            const float* brow = bias + (size_t)(bm + r) * D + bn + wn;
            float* hrow = hs + r * HST + wn;
#pragma unroll
            for (int nf = 0; nf < 4; nf++) {
                int col = nf * 8 + 2 * (lid & 3);
                float2 bv = *(const float2*)(brow + col);
                hrow[col] = tanhf(acc[mf][nf][half * 2 + 0] + bv.x);
                hrow[col + 1] = tanhf(acc[mf][nf][half * 2 + 1] + bv.y);
            }
        }
    }
    __syncthreads();

    // fused child-combine -> Anext columns [bn, bn+128): 512 thr, 8 cols each
    {
        int p = tid >> 4;          // 0..31
        int g = tid & 15;          // 0..15 -> 8-col group
        int pg = (bm >> 2) + p;
        const float* h0 = hs + (4 * p + 0) * HST;
        const float* h1 = hs + (4 * p + 1) * HST;
        const float* h2 = hs + (4 * p + 2) * HST;
        const float* h3 = hs + (4 * p + 3) * HST;
        __half* arow = Anext + (size_t)pg * KA;
        int c0 = g * 8;
        __half lh[8], ll[8], rh[8], rl[8];
#pragma unroll
        for (int j = 0; j < 8; j++) {
            float a = h0[c0 + j], b = h1[c0 + j], c = h2[c0 + j], d = h3[c0 + j];
            float lv = a + (2.f/3.f) * b + (1.f/3.f) * c;
            float rv = (1.f/3.f) * b + (2.f/3.f) * c + d;
            split_fp16(lv, lh[j], ll[j]);
            split_fp16(rv, rh[j], rl[j]);
        }
        int cL = bn + c0;
        *(uint4*)(arow + cL) = *(const uint4*)lh;
        *(uint4*)(arow + 512 + cL) = *(const uint4*)ll;
        *(uint4*)(arow + 256 + cL) = *(const uint4*)rh;
        *(uint4*)(arow + 768 + cL) = *(const uint4*)rl;
    }
}

// ---------------- split-K partial GEMM (l=6,5,4; 2-term 16 chunks) ----------------
__global__ void __launch_bounds__(NTHR, 2)
gemm_partial_kernel(const __half* __restrict__ A,
                    const __half* __restrict__ B,
                    float* __restrict__ P, int M, int cnt) {
    extern __shared__ __align__(128) char smem[];
    const uint32_t sbase = smem_u32(smem);
    const int tid = threadIdx.x;
    const int wid = tid >> 5;
    const int lid = tid & 31;
    const int bn = blockIdx.x * 128;
    const int bm = blockIdx.y * 128;
    const int c0 = blockIdx.z * cnt;

    const char* Ab = (const char*)A + (size_t)bm * ROWA;
    const char* Bb = (const char*)B + (size_t)bn * ROWBB;
    float* Pb = P + ((size_t)blockIdx.z * M + bm) * D + bn;

    float acc[2][4][4];
#pragma unroll
    for (int mf = 0; mf < 2; mf++)
#pragma unroll
        for (int nf = 0; nf < 4; nf++)
#pragma unroll
            for (int q = 0; q < 4; q++) acc[mf][nf][q] = 0.0f;

    const int wm = (wid & 3) * 32;
    const int wn = (wid >> 2) * 32;
    const uint32_t aOff = (uint32_t)(wm + (lid & 7) + ((lid & 8) ? 8 : 0)) * SROW +
                          ((lid & 16) ? 16 : 0);
    const uint32_t bOff = (uint32_t)(wn + (lid & 7) + ((lid & 16) ? 8 : 0)) * SROW +
                          ((lid & 8) ? 16 : 0);

    load_stage_g(sbase, 0, c0, Ab, Bb, tid);
    if (cnt > 1) load_stage_g(sbase, 1, c0 + 1, Ab, Bb, tid);

    for (int i = 0; i < cnt; i++) {
        if (i + 2 < cnt) {
            asm volatile("cp.async.wait_group 1;" ::: "memory");
        } else {
            asm volatile("cp.async.wait_group 0;" ::: "memory");
        }
        __syncthreads();
        if (i + 2 < cnt)
            load_stage_g(sbase, (i + 2) % NSTAGE, c0 + i + 2, Ab, Bb, tid);

        uint32_t sA = sbase + (i % NSTAGE) * STAGE;
        compute_chunk(sA + aOff, sA + TILE_B + bOff, acc);
    }

#pragma unroll
    for (int mf = 0; mf < 2; mf++) {
#pragma unroll
        for (int half = 0; half < 2; half++) {
            int r = wm + mf * 16 + (lid >> 2) + half * 8;
            float* prow = Pb + (size_t)r * D + wn;
#pragma unroll
            for (int nf = 0; nf < 4; nf++) {
                int col = nf * 8 + 2 * (lid & 3);
                float2 o;
                o.x = acc[mf][nf][half * 2 + 0];
                o.y = acc[mf][nf][half * 2 + 1];
                *(float2*)(prow + col) = o;
            }
        }
    }
}

// ---------------- epilogue: sum splits + bias + tanh + combine + split ----------------
__global__ void __launch_bounds__(256)
epilogue_combine_kernel(const float* __restrict__ P, int S,
                        const float* __restrict__ bias,
                        __half* __restrict__ Anext,
                        float* __restrict__ hout, int M) {
    int idx = blockIdx.x * blockDim.x + threadIdx.x;
    int nPar = M >> 2;
    if (idx >= nPar * 64) return;
    int p = idx >> 6;
    int q = idx & 63;

    float4 h[4];
#pragma unroll
    for (int j = 0; j < 4; j++) {
        int row = 4 * p + j;
        float4 sum = *(const float4*)(P + (size_t)row * D + q * 4);
        for (int s = 1; s < S; s++) {
            float4 t = *(const float4*)(P + ((size_t)s * M + row) * D + q * 4);
            sum.x += t.x; sum.y += t.y; sum.z += t.z; sum.w += t.w;
        }
        float4 bv = *(const float4*)(bias + (size_t)row * D + q * 4);
        h[j].x = tanhf(sum.x + bv.x);
        h[j].y = tanhf(sum.y + bv.y);
        h[j].z = tanhf(sum.z + bv.z);
        h[j].w = tanhf(sum.w + bv.w);
        if (hout) *(float4*)(hout + (size_t)row * D + q * 4) = h[j];
    }

    if (Anext) {
        float4 uL, uR;
        uL.x = h[0].x + (2.f/3.f) * h[1].x + (1.f/3.f) * h[2].x;
        uL.y = h[0].y + (2.f/3.f) * h[1].y + (1.f/3.f) * h[2].y;
        uL.z = h[0].z + (2.f/3.f) * h[1].z + (1.f/3.f) * h[2].z;
        uL.w = h[0].w + (2.f/3.f) * h[1].w + (1.f/3.f) * h[2].w;
        uR.x = (1.f/3.f) * h[1].x + (2.f/3.f) * h[2].x + h[3].x;
        uR.y = (1.f/3.f) * h[1].y + (2.f/3.f) * h[2].y + h[3].y;
        uR.z = (1.f/3.f) * h[1].z + (2.f/3.f) * h[2].z + h[3].z;
        uR.w = (1.f/3.f) * h[1].w + (2.f/3.f) * h[2].w + h[3].w;

        __half lh[4], ll[4], rh[4], rl[4];
        split_fp16(uL.x, lh[0], ll[0]);
        split_fp16(uL.y, lh[1], ll[1]);
        split_fp16(uL.z, lh[2], ll[2]);
        split_fp16(uL.w, lh[3], ll[3]);
        split_fp16(uR.x, rh[0], rl[0]);
        split_fp16(uR.y, rh[1], rl[1]);
        split_fp16(uR.z, rh[2], rl[2]);
        split_fp16(uR.w, rh[3], rl[3]);

        __half* arow = Anext + (size_t)p * KA + q * 4;
        *(uint2*)(arow)       = *(const uint2*)lh;
        *(uint2*)(arow + 256) = *(const uint2*)rh;
        *(uint2*)(arow + 512) = *(const uint2*)ll;
        *(uint2*)(arow + 768) = *(const uint2*)rl;
    }
}

// ---------------- small levels (M<=64): fp32 warp-per-output ----------------
__global__ void __launch_bounds__(256)
small_level_kernel(const float* __restrict__ hprev,
                   const float* __restrict__ Wl,
                   const float* __restrict__ Wr,
                   const float* __restrict__ bias,
                   float* __restrict__ hout, int Mout) {
    int gw = (blockIdx.x * blockDim.x + threadIdx.x) >> 5;
    int lid = threadIdx.x & 31;
    if (gw >= Mout * D) return;
    int p = gw >> 8;
    int n = gw & 255;
    const float* h0 = hprev + (size_t)(4 * p) * D;
    const float* wl = Wl + (size_t)n * D;
    const float* wr = Wr + (size_t)n * D;
    float acc = 0.f;
#pragma unroll
    for (int i = 0; i < 8; i++) {
        int k = lid + i * 32;
        float a = h0[k], b = h0[D + k], c = h0[2 * D + k], d = h0[3 * D + k];
        float uL = a + (2.f/3.f) * b + (1.f/3.f) * c;
        float uR = (1.f/3.f) * b + (2.f/3.f) * c + d;
        acc = fmaf(uL, wl[k], acc);
        acc = fmaf(uR, wr[k], acc);
    }
#pragma unroll
    for (int o = 16; o; o >>= 1) acc += __shfl_xor_sync(0xffffffffu, acc, o);
    if (lid == 0)
        hout[(size_t)p * D + n] = tanhf(acc + bias[(size_t)p * D + n]);
}

// ---------------- launcher ----------------
extern "C" void kernel_launch(void* const* d_in, const int* in_sizes, int n_in,
                              void* d_out, int out_size) {
    const float* vectors = (const float*)d_in[0];
    const float* Wl = (const float*)d_in[1];
    const float* Wr = (const float*)d_in[2];
    float* out = (float*)d_out;

    __half *Acat0, *Acat1, *Bcat;
    float *part, *hsA, *hsB;
    cudaGetSymbolAddress((void**)&Acat0, g_Acat0);
    cudaGetSymbolAddress((void**)&Acat1, g_Acat1);
    cudaGetSymbolAddress((void**)&Bcat, g_Bcat);
    cudaGetSymbolAddress((void**)&part, g_part);
    cudaGetSymbolAddress((void**)&hsA, g_hsA);
    cudaGetSymbolAddress((void**)&hsB, g_hsB);

    cudaFuncSetAttribute(gemm_fused_l7,
                         cudaFuncAttributeMaxDynamicSharedMemorySize, SMEM_TOTAL);
    cudaFuncSetAttribute(gemm_fused_l7,
                         cudaFuncAttributePreferredSharedMemoryCarveout, 100);
    cudaFuncSetAttribute(gemm_partial_kernel,
                         cudaFuncAttributeMaxDynamicSharedMemorySize, SMEM_TOTAL);
    cudaFuncSetAttribute(gemm_partial_kernel,
                         cudaFuncAttributePreferredSharedMemoryCarveout, 100);

    prep_w_kernel<<<(D * 512 + 255) / 256, 256>>>(Wl, Wr, Bcat);

    static const int offs[9] = {0, 1, 5, 21, 85, 341, 1365, 5461, 21845};

    const float* leaves = vectors + (size_t)offs[8] * D;
    leaf_reduce_kernel<<<(16384 * 64 + 255) / 256, 256>>>(leaves, Acat0, 16384);

    // l=7: 1-term fused GEMM, Acat0 -> Acat1 (2-term hi/lo written for l=6)
    {
        dim3 grid(2, 128);
        gemm_fused_l7<<<grid, NTHR, SMEM_TOTAL>>>(
            Acat0, Bcat, vectors + (size_t)offs[7] * D, Acat1, 16384);
    }

    // l=6..4: split-K 2-term (S * cnt = 16)
    static const int SPLITS[8] = {0, 0, 0, 0, 16, 8, 4, 0};
    __half* Ain = Acat1;
    for (int l = 6; l >= 4; --l) {
        int M = 1 << (2 * l);
        int S = SPLITS[l];
        int cnt = NCHUNK / S;
        __half* Anext =
            (l > 4) ? ((Ain == Acat0) ? Acat1 : Acat0) : (__half*)nullptr;
        float* hout = (l == 4) ? hsA : nullptr;
        const float* bias = vectors + (size_t)offs[l] * D;

        dim3 grid(2, M / 128, S);
        gemm_partial_kernel<<<grid, NTHR, SMEM_TOTAL>>>(Ain, Bcat, part, M, cnt);

        int nthr = (M / 4) * 64;
        epilogue_combine_kernel<<<(nthr + 255) / 256, 256>>>(part, S, bias, Anext, hout, M);

        Ain = Anext;
    }

    // l=3..0: fp32 SIMT. hsA -> hsB -> hsA -> hsB -> out
    const float* hin = hsA;
    for (int l = 3; l >= 0; --l) {
        int M = 1 << (2 * l);
        float* hout = (l == 0) ? out : ((l & 1) ? hsB : hsA);
        const float* bias = vectors + (size_t)offs[l] * D;
        int nwarps = M * D;
        small_level_kernel<<<(nwarps * 32 + 255) / 256, 256>>>(hin, Wl, Wr, bias, hout, M);
        hin = hout;
    }
}

// round 15
// speedup vs baseline: 1.2238x; 1.0372x over previous
#include <cuda_runtime.h>
#include <cuda_fp16.h>
#include <cstdint>
#include <math.h>

// CBTree B=4, L=9, d=256.
// A=[hi(u)|lo(u)] fp16 (K=1024), B=hi(W) fp16 (K=512).
// l=7: 1-term (8 chunks) fused GEMM (tanh+combine -> Anext, hi only).
// l=6: 1-term (8 chunks) split-K. l=5,4: 2-term (16 chunks) split-K.
// l=3..0: fp32 SIMT.

#define D 256
#define KA 1024
#define ROWA 2048        // A row bytes (1024 fp16)
#define ROWBB 1024       // B row bytes (512 fp16)
#define NCHUNK 16
#define SROW 144
#define TILE_B (128 * SROW)
#define STAGE (2 * TILE_B)            // 36864
#define NSTAGE 3
#define SMEM_TOTAL (NSTAGE * STAGE)   // 110592 (2 CTAs/SM)
#define HST 132
#define NTHR 512

// ---------------- static device scratch ----------------
__device__ __half g_Acat0[16384 * 1024];
__device__ __half g_Acat1[16384 * 1024];
__device__ __half g_Bcat[256 * 512];
__device__ float g_part[16384 * 256];
__device__ float g_hsA[256 * 256];
__device__ float g_hsB[256 * 256];

// ---------------- helpers ----------------
__device__ __forceinline__ uint32_t smem_u32(const void* p) {
    uint32_t a;
    asm("{ .reg .u64 t; cvta.to.shared.u64 t, %1; cvt.u32.u64 %0, t; }" : "=r"(a) : "l"(p));
    return a;
}
__device__ __forceinline__ void cp_async16(uint32_t dst, const void* src) {
    asm volatile("cp.async.cg.shared.global [%0], [%1], 16;" :: "r"(dst), "l"(src));
}
#define CP_COMMIT() asm volatile("cp.async.commit_group;" ::: "memory")

__device__ __forceinline__ void ldm_x4(uint32_t* r, uint32_t addr) {
    asm volatile("ldmatrix.sync.aligned.m8n8.x4.shared.b16 {%0,%1,%2,%3}, [%4];"
                 : "=r"(r[0]), "=r"(r[1]), "=r"(r[2]), "=r"(r[3]) : "r"(addr));
}
__device__ __forceinline__ void mma_f16(float* c, const uint32_t* a, uint32_t b0, uint32_t b1) {
    asm volatile("mma.sync.aligned.m16n8k16.row.col.f32.f16.f16.f32 "
                 "{%0,%1,%2,%3}, {%4,%5,%6,%7}, {%8,%9}, {%0,%1,%2,%3};"
                 : "+f"(c[0]), "+f"(c[1]), "+f"(c[2]), "+f"(c[3])
                 : "r"(a[0]), "r"(a[1]), "r"(a[2]), "r"(a[3]), "r"(b0), "r"(b1));
}
__device__ __forceinline__ void split_fp16(float v, __half& hi, __half& lo) {
    hi = __float2half_rn(v);
    lo = __float2half_rn(v - __half2float(hi));
}

// Per-chunk compute for 32x32 warp tile: 4 ldm_x4 + 8 MMA per kk.
__device__ __forceinline__ void compute_chunk(uint32_t aAddr, uint32_t bAddr,
                                              float acc[2][4][4]) {
#pragma unroll
    for (int kk = 0; kk < 4; kk++) {
        uint32_t a0[4], a1[4], b0[4], b1[4];
        ldm_x4(a0, aAddr + kk * 32);
        ldm_x4(a1, aAddr + 16 * SROW + kk * 32);
        ldm_x4(b0, bAddr + kk * 32);
        ldm_x4(b1, bAddr + 16 * SROW + kk * 32);
        mma_f16(acc[0][0], a0, b0[0], b0[1]);
        mma_f16(acc[0][1], a0, b0[2], b0[3]);
        mma_f16(acc[0][2], a0, b1[0], b1[1]);
        mma_f16(acc[0][3], a0, b1[2], b1[3]);
        mma_f16(acc[1][0], a1, b0[0], b0[1]);
        mma_f16(acc[1][1], a1, b0[2], b0[3]);
        mma_f16(acc[1][2], a1, b1[0], b1[1]);
        mma_f16(acc[1][3], a1, b1[2], b1[3]);
    }
}

// ---------------- prep: Bcat = hi(W) fp16 ----------------
__global__ void prep_w_kernel(const float* __restrict__ Wl,
                              const float* __restrict__ Wr,
                              __half* __restrict__ Bcat) {
    int idx = blockIdx.x * blockDim.x + threadIdx.x;
    if (idx >= D * 512) return;
    int n = idx >> 9;
    int k = idx & 511;
    float w = (k < D) ? Wl[n * D + k] : Wr[n * D + (k - D)];
    Bcat[(size_t)n * 512 + k] = __float2half_rn(w);
}

// ---------------- leaf reduce -> Acat hi halves only (l=7 is 1-term) ----------------
__global__ void __launch_bounds__(256)
leaf_reduce_kernel(const float* __restrict__ h,
                   __half* __restrict__ Acat,
                   int n_par) {
    int idx = blockIdx.x * blockDim.x + threadIdx.x;   // n_par * 64
    if (idx >= n_par * 64) return;
    int p = idx >> 6;
    int q = idx & 63;
    const float4* hp = (const float4*)(h + (size_t)p * 1024);
    float4 a = hp[q];
    float4 b = hp[64 + q];
    float4 c = hp[128 + q];
    float4 d = hp[192 + q];

    __half lh[4], rh[4];
    lh[0] = __float2half_rn(a.x + (2.f/3.f) * b.x + (1.f/3.f) * c.x);
    lh[1] = __float2half_rn(a.y + (2.f/3.f) * b.y + (1.f/3.f) * c.y);
    lh[2] = __float2half_rn(a.z + (2.f/3.f) * b.z + (1.f/3.f) * c.z);
    lh[3] = __float2half_rn(a.w + (2.f/3.f) * b.w + (1.f/3.f) * c.w);
    rh[0] = __float2half_rn((1.f/3.f) * b.x + (2.f/3.f) * c.x + d.x);
    rh[1] = __float2half_rn((1.f/3.f) * b.y + (2.f/3.f) * c.y + d.y);
    rh[2] = __float2half_rn((1.f/3.f) * b.z + (2.f/3.f) * c.z + d.z);
    rh[3] = __float2half_rn((1.f/3.f) * b.w + (2.f/3.f) * c.w + d.w);

    __half* arow = Acat + (size_t)p * KA + q * 4;
    *(uint2*)(arow)       = *(const uint2*)lh;   // hi, k in [0,256)
    *(uint2*)(arow + 256) = *(const uint2*)rh;   // hi, k in [256,512)
}

// ======== stage loader (512 threads): aCh=it, bCh=it&7 ========
__device__ __forceinline__ void load_stage_g(uint32_t sbase, int slot, int it,
                                             const char* Ab, const char* Bb, int tid) {
    int aCh = it;
    int bCh = it & 7;
    uint32_t sA = sbase + slot * STAGE;
    uint32_t sB = sA + TILE_B;
#pragma unroll
    for (int i = 0; i < 2; i++) {
        int id = i * NTHR + tid;
        int r = id >> 3, c = id & 7;
        cp_async16(sA + r * SROW + c * 16, Ab + (size_t)r * ROWA + aCh * 128 + c * 16);
    }
#pragma unroll
    for (int i = 0; i < 2; i++) {
        int id = i * NTHR + tid;
        int r = id >> 3, c = id & 7;
        cp_async16(sB + r * SROW + c * 16, Bb + (size_t)r * ROWBB + bCh * 128 + c * 16);
    }
    CP_COMMIT();
}

// ---------------- l=7: 1-term GEMM (8 chunks) + fused tanh/combine epilogue ----------------
// Anext gets hi halves only (l=6 is 1-term).
__global__ void __launch_bounds__(NTHR, 2)
gemm_fused_l7(const __half* __restrict__ A,
              const __half* __restrict__ B,
              const float* __restrict__ bias,
              __half* __restrict__ Anext, int M) {
    extern __shared__ __align__(128) char smem[];
    const uint32_t sbase = smem_u32(smem);
    const int tid = threadIdx.x;
    const int wid = tid >> 5;
    const int lid = tid & 31;
    const int bn = blockIdx.x * 128;
    const int bm = blockIdx.y * 128;

    const char* Ab = (const char*)A + (size_t)bm * ROWA;
    const char* Bb = (const char*)B + (size_t)bn * ROWBB;

    float acc[2][4][4];
#pragma unroll
    for (int mf = 0; mf < 2; mf++)
#pragma unroll
        for (int nf = 0; nf < 4; nf++)
#pragma unroll
            for (int q = 0; q < 4; q++) acc[mf][nf][q] = 0.0f;

    const int wm = (wid & 3) * 32;
    const int wn = (wid >> 2) * 32;
    const uint32_t aOff = (uint32_t)(wm + (lid & 7) + ((lid & 8) ? 8 : 0)) * SROW +
                          ((lid & 16) ? 16 : 0);
    const uint32_t bOff = (uint32_t)(wn + (lid & 7) + ((lid & 16) ? 8 : 0)) * SROW +
                          ((lid & 8) ? 16 : 0);

    const int NCH = 8;   // 1-term: hi chunks only
    load_stage_g(sbase, 0, 0, Ab, Bb, tid);
    load_stage_g(sbase, 1, 1, Ab, Bb, tid);

    for (int it = 0; it < NCH; it++) {
        if (it + 2 < NCH) {
            asm volatile("cp.async.wait_group 1;" ::: "memory");
        } else {
            asm volatile("cp.async.wait_group 0;" ::: "memory");
        }
        __syncthreads();
        if (it + 2 < NCH)
            load_stage_g(sbase, (it + 2) % NSTAGE, it + 2, Ab, Bb, tid);

        uint32_t sA = sbase + (it % NSTAGE) * STAGE;
        compute_chunk(sA + aOff, sA + TILE_B + bOff, acc);
    }
    __syncthreads();

    // epilogue: tanh(acc+bias) -> smem h tile
    float* hs = (float*)smem;
#pragma unroll
    for (int mf = 0; mf < 2; mf++) {
#pragma unroll
        for (int half = 0; half < 2; half++) {
            int r = wm + mf * 16 + (lid >> 2) + half * 8;
            const float* brow = bias + (size_t)(bm + r) * D + bn + wn;
            float* hrow = hs + r * HST + wn;
#pragma unroll
            for (int nf = 0; nf < 4; nf++) {
                int col = nf * 8 + 2 * (lid & 3);
                float2 bv = *(const float2*)(brow + col);
                hrow[col] = tanhf(acc[mf][nf][half * 2 + 0] + bv.x);
                hrow[col + 1] = tanhf(acc[mf][nf][half * 2 + 1] + bv.y);
            }
        }
    }
    __syncthreads();

    // fused child-combine -> Anext hi columns [bn, bn+128): 512 thr, 8 cols each
    {
        int p = tid >> 4;          // 0..31
        int g = tid & 15;          // 0..15 -> 8-col group
        int pg = (bm >> 2) + p;
        const float* h0 = hs + (4 * p + 0) * HST;
        const float* h1 = hs + (4 * p + 1) * HST;
        const float* h2 = hs + (4 * p + 2) * HST;
        const float* h3 = hs + (4 * p + 3) * HST;
        __half* arow = Anext + (size_t)pg * KA;
        int c0 = g * 8;
        __half lh[8], rh[8];
#pragma unroll
        for (int j = 0; j < 8; j++) {
            float a = h0[c0 + j], b = h1[c0 + j], c = h2[c0 + j], d = h3[c0 + j];
            lh[j] = __float2half_rn(a + (2.f/3.f) * b + (1.f/3.f) * c);
            rh[j] = __float2half_rn((1.f/3.f) * b + (2.f/3.f) * c + d);
        }
        int cL = bn + c0;
        *(uint4*)(arow + cL) = *(const uint4*)lh;
        *(uint4*)(arow + 256 + cL) = *(const uint4*)rh;
    }
}

// ---------------- split-K partial GEMM (l=6: chunks 0-7; l=5,4: 0-15) ----------------
__global__ void __launch_bounds__(NTHR, 2)
gemm_partial_kernel(const __half* __restrict__ A,
                    const __half* __restrict__ B,
                    float* __restrict__ P, int M, int cnt) {
    extern __shared__ __align__(128) char smem[];
    const uint32_t sbase = smem_u32(smem);
    const int tid = threadIdx.x;
    const int wid = tid >> 5;
    const int lid = tid & 31;
    const int bn = blockIdx.x * 128;
    const int bm = blockIdx.y * 128;
    const int c0 = blockIdx.z * cnt;

    const char* Ab = (const char*)A + (size_t)bm * ROWA;
    const char* Bb = (const char*)B + (size_t)bn * ROWBB;
    float* Pb = P + ((size_t)blockIdx.z * M + bm) * D + bn;

    float acc[2][4][4];
#pragma unroll
    for (int mf = 0; mf < 2; mf++)
#pragma unroll
        for (int nf = 0; nf < 4; nf++)
#pragma unroll
            for (int q = 0; q < 4; q++) acc[mf][nf][q] = 0.0f;

    const int wm = (wid & 3) * 32;
    const int wn = (wid >> 2) * 32;
    const uint32_t aOff = (uint32_t)(wm + (lid & 7) + ((lid & 8) ? 8 : 0)) * SROW +
                          ((lid & 16) ? 16 : 0);
    const uint32_t bOff = (uint32_t)(wn + (lid & 7) + ((lid & 16) ? 8 : 0)) * SROW +
                          ((lid & 8) ? 16 : 0);

    load_stage_g(sbase, 0, c0, Ab, Bb, tid);
    if (cnt > 1) load_stage_g(sbase, 1, c0 + 1, Ab, Bb, tid);

    for (int i = 0; i < cnt; i++) {
        if (i + 2 < cnt) {
            asm volatile("cp.async.wait_group 1;" ::: "memory");
        } else {
            asm volatile("cp.async.wait_group 0;" ::: "memory");
        }
        __syncthreads();
        if (i + 2 < cnt)
            load_stage_g(sbase, (i + 2) % NSTAGE, c0 + i + 2, Ab, Bb, tid);

        uint32_t sA = sbase + (i % NSTAGE) * STAGE;
        compute_chunk(sA + aOff, sA + TILE_B + bOff, acc);
    }

#pragma unroll
    for (int mf = 0; mf < 2; mf++) {
#pragma unroll
        for (int half = 0; half < 2; half++) {
            int r = wm + mf * 16 + (lid >> 2) + half * 8;
            float* prow = Pb + (size_t)r * D + wn;
#pragma unroll
            for (int nf = 0; nf < 4; nf++) {
                int col = nf * 8 + 2 * (lid & 3);
                float2 o;
                o.x = acc[mf][nf][half * 2 + 0];
                o.y = acc[mf][nf][half * 2 + 1];
                *(float2*)(prow + col) = o;
            }
        }
    }
}

// ---------------- epilogue: sum splits + bias + tanh + combine + split ----------------
__global__ void __launch_bounds__(256)
epilogue_combine_kernel(const float* __restrict__ P, int S,
                        const float* __restrict__ bias,
                        __half* __restrict__ Anext,
                        float* __restrict__ hout, int M) {
    int idx = blockIdx.x * blockDim.x + threadIdx.x;
    int nPar = M >> 2;
    if (idx >= nPar * 64) return;
    int p = idx >> 6;
    int q = idx & 63;

    float4 h[4];
#pragma unroll
    for (int j = 0; j < 4; j++) {
        int row = 4 * p + j;
        float4 sum = *(const float4*)(P + (size_t)row * D + q * 4);
        for (int s = 1; s < S; s++) {
            float4 t = *(const float4*)(P + ((size_t)s * M + row) * D + q * 4);
            sum.x += t.x; sum.y += t.y; sum.z += t.z; sum.w += t.w;
        }
        float4 bv = *(const float4*)(bias + (size_t)row * D + q * 4);
        h[j].x = tanhf(sum.x + bv.x);
        h[j].y = tanhf(sum.y + bv.y);
        h[j].z = tanhf(sum.z + bv.z);
        h[j].w = tanhf(sum.w + bv.w);
        if (hout) *(float4*)(hout + (size_t)row * D + q * 4) = h[j];
    }

    if (Anext) {
        float4 uL, uR;
        uL.x = h[0].x + (2.f/3.f) * h[1].x + (1.f/3.f) * h[2].x;
        uL.y = h[0].y + (2.f/3.f) * h[1].y + (1.f/3.f) * h[2].y;
        uL.z = h[0].z + (2.f/3.f) * h[1].z + (1.f/3.f) * h[2].z;
        uL.w = h[0].w + (2.f/3.f) * h[1].w + (1.f/3.f) * h[2].w;
        uR.x = (1.f/3.f) * h[1].x + (2.f/3.f) * h[2].x + h[3].x;
        uR.y = (1.f/3.f) * h[1].y + (2.f/3.f) * h[2].y + h[3].y;
        uR.z = (1.f/3.f) * h[1].z + (2.f/3.f) * h[2].z + h[3].z;
        uR.w = (1.f/3.f) * h[1].w + (2.f/3.f) * h[2].w + h[3].w;

        __half lh[4], ll[4], rh[4], rl[4];
        split_fp16(uL.x, lh[0], ll[0]);
        split_fp16(uL.y, lh[1], ll[1]);
        split_fp16(uL.z, lh[2], ll[2]);
        split_fp16(uL.w, lh[3], ll[3]);
        split_fp16(uR.x, rh[0], rl[0]);
        split_fp16(uR.y, rh[1], rl[1]);
        split_fp16(uR.z, rh[2], rl[2]);
        split_fp16(uR.w, rh[3], rl[3]);

        __half* arow = Anext + (size_t)p * KA + q * 4;
        *(uint2*)(arow)       = *(const uint2*)lh;
        *(uint2*)(arow + 256) = *(const uint2*)rh;
        *(uint2*)(arow + 512) = *(const uint2*)ll;
        *(uint2*)(arow + 768) = *(const uint2*)rl;
    }
}

// ---------------- small levels (M<=64): fp32 warp-per-output ----------------
__global__ void __launch_bounds__(256)
small_level_kernel(const float* __restrict__ hprev,
                   const float* __restrict__ Wl,
                   const float* __restrict__ Wr,
                   const float* __restrict__ bias,
                   float* __restrict__ hout, int Mout) {
    int gw = (blockIdx.x * blockDim.x + threadIdx.x) >> 5;
    int lid = threadIdx.x & 31;
    if (gw >= Mout * D) return;
    int p = gw >> 8;
    int n = gw & 255;
    const float* h0 = hprev + (size_t)(4 * p) * D;
    const float* wl = Wl + (size_t)n * D;
    const float* wr = Wr + (size_t)n * D;
    float acc = 0.f;
#pragma unroll
    for (int i = 0; i < 8; i++) {
        int k = lid + i * 32;
        float a = h0[k], b = h0[D + k], c = h0[2 * D + k], d = h0[3 * D + k];
        float uL = a + (2.f/3.f) * b + (1.f/3.f) * c;
        float uR = (1.f/3.f) * b + (2.f/3.f) * c + d;
        acc = fmaf(uL, wl[k], acc);
        acc = fmaf(uR, wr[k], acc);
    }
#pragma unroll
    for (int o = 16; o; o >>= 1) acc += __shfl_xor_sync(0xffffffffu, acc, o);
    if (lid == 0)
        hout[(size_t)p * D + n] = tanhf(acc + bias[(size_t)p * D + n]);
}

// ---------------- launcher ----------------
extern "C" void kernel_launch(void* const* d_in, const int* in_sizes, int n_in,
                              void* d_out, int out_size) {
    const float* vectors = (const float*)d_in[0];
    const float* Wl = (const float*)d_in[1];
    const float* Wr = (const float*)d_in[2];
    float* out = (float*)d_out;

    __half *Acat0, *Acat1, *Bcat;
    float *part, *hsA, *hsB;
    cudaGetSymbolAddress((void**)&Acat0, g_Acat0);
    cudaGetSymbolAddress((void**)&Acat1, g_Acat1);
    cudaGetSymbolAddress((void**)&Bcat, g_Bcat);
    cudaGetSymbolAddress((void**)&part, g_part);
    cudaGetSymbolAddress((void**)&hsA, g_hsA);
    cudaGetSymbolAddress((void**)&hsB, g_hsB);

    cudaFuncSetAttribute(gemm_fused_l7,
                         cudaFuncAttributeMaxDynamicSharedMemorySize, SMEM_TOTAL);
    cudaFuncSetAttribute(gemm_fused_l7,
                         cudaFuncAttributePreferredSharedMemoryCarveout, 100);
    cudaFuncSetAttribute(gemm_partial_kernel,
                         cudaFuncAttributeMaxDynamicSharedMemorySize, SMEM_TOTAL);
    cudaFuncSetAttribute(gemm_partial_kernel,
                         cudaFuncAttributePreferredSharedMemoryCarveout, 100);

    prep_w_kernel<<<(D * 512 + 255) / 256, 256>>>(Wl, Wr, Bcat);

    static const int offs[9] = {0, 1, 5, 21, 85, 341, 1365, 5461, 21845};

    const float* leaves = vectors + (size_t)offs[8] * D;
    leaf_reduce_kernel<<<(16384 * 64 + 255) / 256, 256>>>(leaves, Acat0, 16384);

    // l=7: 1-term fused GEMM, Acat0 -> Acat1 (hi halves only)
    {
        dim3 grid(2, 128);
        gemm_fused_l7<<<grid, NTHR, SMEM_TOTAL>>>(
            Acat0, Bcat, vectors + (size_t)offs[7] * D, Acat1, 16384);
    }

    // l=6: 1-term split-K (chunks 0-7), S=4 cnt=2, Acat1 -> Acat0 (hi+lo for l=5)
    {
        int M = 4096, S = 4, cnt = 2;
        dim3 grid(2, M / 128, S);
        gemm_partial_kernel<<<grid, NTHR, SMEM_TOTAL>>>(Acat1, Bcat, part, M, cnt);
        int nthr = (M / 4) * 64;
        epilogue_combine_kernel<<<(nthr + 255) / 256, 256>>>(
            part, S, vectors + (size_t)offs[6] * D, Acat0, nullptr, M);
    }

    // l=5: 2-term split-K (chunks 0-15), S=8 cnt=2, Acat0 -> Acat1
    {
        int M = 1024, S = 8, cnt = 2;
        dim3 grid(2, M / 128, S);
        gemm_partial_kernel<<<grid, NTHR, SMEM_TOTAL>>>(Acat0, Bcat, part, M, cnt);
        int nthr = (M / 4) * 64;
        epilogue_combine_kernel<<<(nthr + 255) / 256, 256>>>(
            part, S, vectors + (size_t)offs[5] * D, Acat1, nullptr, M);
    }

    // l=4: 2-term split-K, S=16 cnt=1, Acat1 -> fp32 h (hsA)
    {
        int M = 256, S = 16, cnt = 1;
        dim3 grid(2, M / 128, S);
        gemm_partial_kernel<<<grid, NTHR, SMEM_TOTAL>>>(Acat1, Bcat, part, M, cnt);
        int nthr = (M / 4) * 64;
        epilogue_combine_kernel<<<(nthr + 255) / 256, 256>>>(
            part, S, vectors + (size_t)offs[4] * D, nullptr, hsA, M);
    }

    // l=3..0: fp32 SIMT. hsA -> hsB -> hsA -> hsB -> out
    const float* hin = hsA;
    for (int l = 3; l >= 0; --l) {
        int M = 1 << (2 * l);
        float* hout = (l == 0) ? out : ((l & 1) ? hsB : hsA);
        const float* bias = vectors + (size_t)offs[l] * D;
        int nwarps = M * D;
        small_level_kernel<<<(nwarps * 32 + 255) / 256, 256>>>(hin, Wl, Wr, bias, hout, M);
        hin = hout;
    }
}

// round 16
// speedup vs baseline: 1.2767x; 1.0432x over previous
#include <cuda_runtime.h>
#include <cuda_fp16.h>
#include <cstdint>
#include <math.h>

// CBTree B=4, L=9, d=256.
// 1-term fp16 everywhere on tensor-core levels: A=hi(u) (K=512), B=hi(W) (K=512).
// 8 chunks of 64. l=7: fused GEMM (tanh+combine -> Anext). l=6,5,4: split-K +
// epilogue (hi-only writes). l=3..0: fp32 SIMT warp-per-output.

#define D 256
#define KA 1024          // Acat row stride in elements (layout kept; lo unused)
#define ROWA 2048        // A row bytes
#define ROWBB 1024       // B row bytes (512 fp16)
#define NCH 8
#define SROW 144
#define TILE_B (128 * SROW)
#define STAGE (2 * TILE_B)            // 36864
#define NSTAGE 3
#define SMEM_TOTAL (NSTAGE * STAGE)   // 110592 (2 CTAs/SM)
#define HST 132
#define NTHR 512

// ---------------- static device scratch ----------------
__device__ __half g_Acat0[16384 * 1024];
__device__ __half g_Acat1[16384 * 1024];
__device__ __half g_Bcat[256 * 512];
__device__ float g_part[16384 * 256];
__device__ float g_hsA[256 * 256];
__device__ float g_hsB[256 * 256];

// ---------------- helpers ----------------
__device__ __forceinline__ uint32_t smem_u32(const void* p) {
    uint32_t a;
    asm("{ .reg .u64 t; cvta.to.shared.u64 t, %1; cvt.u32.u64 %0, t; }" : "=r"(a) : "l"(p));
    return a;
}
__device__ __forceinline__ void cp_async16(uint32_t dst, const void* src) {
    asm volatile("cp.async.cg.shared.global [%0], [%1], 16;" :: "r"(dst), "l"(src));
}
#define CP_COMMIT() asm volatile("cp.async.commit_group;" ::: "memory")

__device__ __forceinline__ void ldm_x4(uint32_t* r, uint32_t addr) {
    asm volatile("ldmatrix.sync.aligned.m8n8.x4.shared.b16 {%0,%1,%2,%3}, [%4];"
                 : "=r"(r[0]), "=r"(r[1]), "=r"(r[2]), "=r"(r[3]) : "r"(addr));
}
__device__ __forceinline__ void mma_f16(float* c, const uint32_t* a, uint32_t b0, uint32_t b1) {
    asm volatile("mma.sync.aligned.m16n8k16.row.col.f32.f16.f16.f32 "
                 "{%0,%1,%2,%3}, {%4,%5,%6,%7}, {%8,%9}, {%0,%1,%2,%3};"
                 : "+f"(c[0]), "+f"(c[1]), "+f"(c[2]), "+f"(c[3])
                 : "r"(a[0]), "r"(a[1]), "r"(a[2]), "r"(a[3]), "r"(b0), "r"(b1));
}

// Per-chunk compute for 32x32 warp tile: 4 ldm_x4 + 8 MMA per kk.
__device__ __forceinline__ void compute_chunk(uint32_t aAddr, uint32_t bAddr,
                                              float acc[2][4][4]) {
#pragma unroll
    for (int kk = 0; kk < 4; kk++) {
        uint32_t a0[4], a1[4], b0[4], b1[4];
        ldm_x4(a0, aAddr + kk * 32);
        ldm_x4(a1, aAddr + 16 * SROW + kk * 32);
        ldm_x4(b0, bAddr + kk * 32);
        ldm_x4(b1, bAddr + 16 * SROW + kk * 32);
        mma_f16(acc[0][0], a0, b0[0], b0[1]);
        mma_f16(acc[0][1], a0, b0[2], b0[3]);
        mma_f16(acc[0][2], a0, b1[0], b1[1]);
        mma_f16(acc[0][3], a0, b1[2], b1[3]);
        mma_f16(acc[1][0], a1, b0[0], b0[1]);
        mma_f16(acc[1][1], a1, b0[2], b0[3]);
        mma_f16(acc[1][2], a1, b1[0], b1[1]);
        mma_f16(acc[1][3], a1, b1[2], b1[3]);
    }
}

// ---------------- prep: Bcat = hi(W) fp16 ----------------
__global__ void prep_w_kernel(const float* __restrict__ Wl,
                              const float* __restrict__ Wr,
                              __half* __restrict__ Bcat) {
    int idx = blockIdx.x * blockDim.x + threadIdx.x;
    if (idx >= D * 512) return;
    int n = idx >> 9;
    int k = idx & 511;
    float w = (k < D) ? Wl[n * D + k] : Wr[n * D + (k - D)];
    Bcat[(size_t)n * 512 + k] = __float2half_rn(w);
}

// ---------------- leaf reduce -> Acat hi halves ----------------
__global__ void __launch_bounds__(256)
leaf_reduce_kernel(const float* __restrict__ h,
                   __half* __restrict__ Acat,
                   int n_par) {
    int idx = blockIdx.x * blockDim.x + threadIdx.x;   // n_par * 64
    if (idx >= n_par * 64) return;
    int p = idx >> 6;
    int q = idx & 63;
    const float4* hp = (const float4*)(h + (size_t)p * 1024);
    float4 a = hp[q];
    float4 b = hp[64 + q];
    float4 c = hp[128 + q];
    float4 d = hp[192 + q];

    __half lh[4], rh[4];
    lh[0] = __float2half_rn(a.x + (2.f/3.f) * b.x + (1.f/3.f) * c.x);
    lh[1] = __float2half_rn(a.y + (2.f/3.f) * b.y + (1.f/3.f) * c.y);
    lh[2] = __float2half_rn(a.z + (2.f/3.f) * b.z + (1.f/3.f) * c.z);
    lh[3] = __float2half_rn(a.w + (2.f/3.f) * b.w + (1.f/3.f) * c.w);
    rh[0] = __float2half_rn((1.f/3.f) * b.x + (2.f/3.f) * c.x + d.x);
    rh[1] = __float2half_rn((1.f/3.f) * b.y + (2.f/3.f) * c.y + d.y);
    rh[2] = __float2half_rn((1.f/3.f) * b.z + (2.f/3.f) * c.z + d.z);
    rh[3] = __float2half_rn((1.f/3.f) * b.w + (2.f/3.f) * c.w + d.w);

    __half* arow = Acat + (size_t)p * KA + q * 4;
    *(uint2*)(arow)       = *(const uint2*)lh;   // k in [0,256)
    *(uint2*)(arow + 256) = *(const uint2*)rh;   // k in [256,512)
}

// ======== stage loader (512 threads): chunks 0..7 of the hi half ========
__device__ __forceinline__ void load_stage_g(uint32_t sbase, int slot, int it,
                                             const char* Ab, const char* Bb, int tid) {
    uint32_t sA = sbase + slot * STAGE;
    uint32_t sB = sA + TILE_B;
#pragma unroll
    for (int i = 0; i < 2; i++) {
        int id = i * NTHR + tid;
        int r = id >> 3, c = id & 7;
        cp_async16(sA + r * SROW + c * 16, Ab + (size_t)r * ROWA + it * 128 + c * 16);
    }
#pragma unroll
    for (int i = 0; i < 2; i++) {
        int id = i * NTHR + tid;
        int r = id >> 3, c = id & 7;
        cp_async16(sB + r * SROW + c * 16, Bb + (size_t)r * ROWBB + it * 128 + c * 16);
    }
    CP_COMMIT();
}

// ---------------- l=7: GEMM (8 chunks) + fused tanh/combine epilogue ----------------
__global__ void __launch_bounds__(NTHR, 2)
gemm_fused_l7(const __half* __restrict__ A,
              const __half* __restrict__ B,
              const float* __restrict__ bias,
              __half* __restrict__ Anext, int M) {
    extern __shared__ __align__(128) char smem[];
    const uint32_t sbase = smem_u32(smem);
    const int tid = threadIdx.x;
    const int wid = tid >> 5;
    const int lid = tid & 31;
    const int bn = blockIdx.x * 128;
    const int bm = blockIdx.y * 128;

    const char* Ab = (const char*)A + (size_t)bm * ROWA;
    const char* Bb = (const char*)B + (size_t)bn * ROWBB;

    float acc[2][4][4];
#pragma unroll
    for (int mf = 0; mf < 2; mf++)
#pragma unroll
        for (int nf = 0; nf < 4; nf++)
#pragma unroll
            for (int q = 0; q < 4; q++) acc[mf][nf][q] = 0.0f;

    const int wm = (wid & 3) * 32;
    const int wn = (wid >> 2) * 32;
    const uint32_t aOff = (uint32_t)(wm + (lid & 7) + ((lid & 8) ? 8 : 0)) * SROW +
                          ((lid & 16) ? 16 : 0);
    const uint32_t bOff = (uint32_t)(wn + (lid & 7) + ((lid & 16) ? 8 : 0)) * SROW +
                          ((lid & 8) ? 16 : 0);

    load_stage_g(sbase, 0, 0, Ab, Bb, tid);
    load_stage_g(sbase, 1, 1, Ab, Bb, tid);

    for (int it = 0; it < NCH; it++) {
        if (it + 2 < NCH) {
            asm volatile("cp.async.wait_group 1;" ::: "memory");
        } else {
            asm volatile("cp.async.wait_group 0;" ::: "memory");
        }
        __syncthreads();
        if (it + 2 < NCH)
            load_stage_g(sbase, (it + 2) % NSTAGE, it + 2, Ab, Bb, tid);

        uint32_t sA = sbase + (it % NSTAGE) * STAGE;
        compute_chunk(sA + aOff, sA + TILE_B + bOff, acc);
    }
    __syncthreads();

    // epilogue: tanh(acc+bias) -> smem h tile
    float* hs = (float*)smem;
#pragma unroll
    for (int mf = 0; mf < 2; mf++) {
#pragma unroll
        for (int half = 0; half < 2; half++) {
            int r = wm + mf * 16 + (lid >> 2) + half * 8;
            const float* brow = bias + (size_t)(bm + r) * D + bn + wn;
            float* hrow = hs + r * HST + wn;
#pragma unroll
            for (int nf = 0; nf < 4; nf++) {
                int col = nf * 8 + 2 * (lid & 3);
                float2 bv = *(const float2*)(brow + col);
                hrow[col] = tanhf(acc[mf][nf][half * 2 + 0] + bv.x);
                hrow[col + 1] = tanhf(acc[mf][nf][half * 2 + 1] + bv.y);
            }
        }
    }
    __syncthreads();

    // fused child-combine -> Anext hi columns [bn, bn+128)
    {
        int p = tid >> 4;          // 0..31
        int g = tid & 15;          // 0..15 -> 8-col group
        int pg = (bm >> 2) + p;
        const float* h0 = hs + (4 * p + 0) * HST;
        const float* h1 = hs + (4 * p + 1) * HST;
        const float* h2 = hs + (4 * p + 2) * HST;
        const float* h3 = hs + (4 * p + 3) * HST;
        __half* arow = Anext + (size_t)pg * KA;
        int c0 = g * 8;
        __half lh[8], rh[8];
#pragma unroll
        for (int j = 0; j < 8; j++) {
            float a = h0[c0 + j], b = h1[c0 + j], c = h2[c0 + j], d = h3[c0 + j];
            lh[j] = __float2half_rn(a + (2.f/3.f) * b + (1.f/3.f) * c);
            rh[j] = __float2half_rn((1.f/3.f) * b + (2.f/3.f) * c + d);
        }
        int cL = bn + c0;
        *(uint4*)(arow + cL) = *(const uint4*)lh;
        *(uint4*)(arow + 256 + cL) = *(const uint4*)rh;
    }
}

// ---------------- split-K partial GEMM (l=6,5,4) ----------------
__global__ void __launch_bounds__(NTHR, 2)
gemm_partial_kernel(const __half* __restrict__ A,
                    const __half* __restrict__ B,
                    float* __restrict__ P, int M, int cnt) {
    extern __shared__ __align__(128) char smem[];
    const uint32_t sbase = smem_u32(smem);
    const int tid = threadIdx.x;
    const int wid = tid >> 5;
    const int lid = tid & 31;
    const int bn = blockIdx.x * 128;
    const int bm = blockIdx.y * 128;
    const int c0 = blockIdx.z * cnt;

    const char* Ab = (const char*)A + (size_t)bm * ROWA;
    const char* Bb = (const char*)B + (size_t)bn * ROWBB;
    float* Pb = P + ((size_t)blockIdx.z * M + bm) * D + bn;

    float acc[2][4][4];
#pragma unroll
    for (int mf = 0; mf < 2; mf++)
#pragma unroll
        for (int nf = 0; nf < 4; nf++)
#pragma unroll
            for (int q = 0; q < 4; q++) acc[mf][nf][q] = 0.0f;

    const int wm = (wid & 3) * 32;
    const int wn = (wid >> 2) * 32;
    const uint32_t aOff = (uint32_t)(wm + (lid & 7) + ((lid & 8) ? 8 : 0)) * SROW +
                          ((lid & 16) ? 16 : 0);
    const uint32_t bOff = (uint32_t)(wn + (lid & 7) + ((lid & 16) ? 8 : 0)) * SROW +
                          ((lid & 8) ? 16 : 0);

    load_stage_g(sbase, 0, c0, Ab, Bb, tid);
    if (cnt > 1) load_stage_g(sbase, 1, c0 + 1, Ab, Bb, tid);

    for (int i = 0; i < cnt; i++) {
        if (i + 2 < cnt) {
            asm volatile("cp.async.wait_group 1;" ::: "memory");
        } else {
            asm volatile("cp.async.wait_group 0;" ::: "memory");
        }
        __syncthreads();
        if (i + 2 < cnt)
            load_stage_g(sbase, (i + 2) % NSTAGE, c0 + i + 2, Ab, Bb, tid);

        uint32_t sA = sbase + (i % NSTAGE) * STAGE;
        compute_chunk(sA + aOff, sA + TILE_B + bOff, acc);
    }

#pragma unroll
    for (int mf = 0; mf < 2; mf++) {
#pragma unroll
        for (int half = 0; half < 2; half++) {
            int r = wm + mf * 16 + (lid >> 2) + half * 8;
            float* prow = Pb + (size_t)r * D + wn;
#pragma unroll
            for (int nf = 0; nf < 4; nf++) {
                int col = nf * 8 + 2 * (lid & 3);
                float2 o;
                o.x = acc[mf][nf][half * 2 + 0];
                o.y = acc[mf][nf][half * 2 + 1];
                *(float2*)(prow + col) = o;
            }
        }
    }
}

// ---------------- epilogue: sum splits + bias + tanh + combine (hi-only) ----------------
__global__ void __launch_bounds__(256)
epilogue_combine_kernel(const float* __restrict__ P, int S,
                        const float* __restrict__ bias,
                        __half* __restrict__ Anext,
                        float* __restrict__ hout, int M) {
    int idx = blockIdx.x * blockDim.x + threadIdx.x;
    int nPar = M >> 2;
    if (idx >= nPar * 64) return;
    int p = idx >> 6;
    int q = idx & 63;

    float4 h[4];
#pragma unroll
    for (int j = 0; j < 4; j++) {
        int row = 4 * p + j;
        float4 sum = *(const float4*)(P + (size_t)row * D + q * 4);
        for (int s = 1; s < S; s++) {
            float4 t = *(const float4*)(P + ((size_t)s * M + row) * D + q * 4);
            sum.x += t.x; sum.y += t.y; sum.z += t.z; sum.w += t.w;
        }
        float4 bv = *(const float4*)(bias + (size_t)row * D + q * 4);
        h[j].x = tanhf(sum.x + bv.x);
        h[j].y = tanhf(sum.y + bv.y);
        h[j].z = tanhf(sum.z + bv.z);
        h[j].w = tanhf(sum.w + bv.w);
        if (hout) *(float4*)(hout + (size_t)row * D + q * 4) = h[j];
    }

    if (Anext) {
        __half lh[4], rh[4];
        lh[0] = __float2half_rn(h[0].x + (2.f/3.f) * h[1].x + (1.f/3.f) * h[2].x);
        lh[1] = __float2half_rn(h[0].y + (2.f/3.f) * h[1].y + (1.f/3.f) * h[2].y);
        lh[2] = __float2half_rn(h[0].z + (2.f/3.f) * h[1].z + (1.f/3.f) * h[2].z);
        lh[3] = __float2half_rn(h[0].w + (2.f/3.f) * h[1].w + (1.f/3.f) * h[2].w);
        rh[0] = __float2half_rn((1.f/3.f) * h[1].x + (2.f/3.f) * h[2].x + h[3].x);
        rh[1] = __float2half_rn((1.f/3.f) * h[1].y + (2.f/3.f) * h[2].y + h[3].y);
        rh[2] = __float2half_rn((1.f/3.f) * h[1].z + (2.f/3.f) * h[2].z + h[3].z);
        rh[3] = __float2half_rn((1.f/3.f) * h[1].w + (2.f/3.f) * h[2].w + h[3].w);

        __half* arow = Anext + (size_t)p * KA + q * 4;
        *(uint2*)(arow)       = *(const uint2*)lh;
        *(uint2*)(arow + 256) = *(const uint2*)rh;
    }
}

// ---------------- small levels (M<=64): fp32 warp-per-output ----------------
__global__ void __launch_bounds__(256)
small_level_kernel(const float* __restrict__ hprev,
                   const float* __restrict__ Wl,
                   const float* __restrict__ Wr,
                   const float* __restrict__ bias,
                   float* __restrict__ hout, int Mout) {
    int gw = (blockIdx.x * blockDim.x + threadIdx.x) >> 5;
    int lid = threadIdx.x & 31;
    if (gw >= Mout * D) return;
    int p = gw >> 8;
    int n = gw & 255;
    const float* h0 = hprev + (size_t)(4 * p) * D;
    const float* wl = Wl + (size_t)n * D;
    const float* wr = Wr + (size_t)n * D;
    float acc = 0.f;
#pragma unroll
    for (int i = 0; i < 8; i++) {
        int k = lid + i * 32;
        float a = h0[k], b = h0[D + k], c = h0[2 * D + k], d = h0[3 * D + k];
        float uL = a + (2.f/3.f) * b + (1.f/3.f) * c;
        float uR = (1.f/3.f) * b + (2.f/3.f) * c + d;
        acc = fmaf(uL, wl[k], acc);
        acc = fmaf(uR, wr[k], acc);
    }
#pragma unroll
    for (int o = 16; o; o >>= 1) acc += __shfl_xor_sync(0xffffffffu, acc, o);
    if (lid == 0)
        hout[(size_t)p * D + n] = tanhf(acc + bias[(size_t)p * D + n]);
}

// ---------------- launcher ----------------
extern "C" void kernel_launch(void* const* d_in, const int* in_sizes, int n_in,
                              void* d_out, int out_size) {
    const float* vectors = (const float*)d_in[0];
    const float* Wl = (const float*)d_in[1];
    const float* Wr = (const float*)d_in[2];
    float* out = (float*)d_out;

    __half *Acat0, *Acat1, *Bcat;
    float *part, *hsA, *hsB;
    cudaGetSymbolAddress((void**)&Acat0, g_Acat0);
    cudaGetSymbolAddress((void**)&Acat1, g_Acat1);
    cudaGetSymbolAddress((void**)&Bcat, g_Bcat);
    cudaGetSymbolAddress((void**)&part, g_part);
    cudaGetSymbolAddress((void**)&hsA, g_hsA);
    cudaGetSymbolAddress((void**)&hsB, g_hsB);

    cudaFuncSetAttribute(gemm_fused_l7,
                         cudaFuncAttributeMaxDynamicSharedMemorySize, SMEM_TOTAL);
    cudaFuncSetAttribute(gemm_fused_l7,
                         cudaFuncAttributePreferredSharedMemoryCarveout, 100);
    cudaFuncSetAttribute(gemm_partial_kernel,
                         cudaFuncAttributeMaxDynamicSharedMemorySize, SMEM_TOTAL);
    cudaFuncSetAttribute(gemm_partial_kernel,
                         cudaFuncAttributePreferredSharedMemoryCarveout, 100);

    prep_w_kernel<<<(D * 512 + 255) / 256, 256>>>(Wl, Wr, Bcat);

    static const int offs[9] = {0, 1, 5, 21, 85, 341, 1365, 5461, 21845};

    const float* leaves = vectors + (size_t)offs[8] * D;
    leaf_reduce_kernel<<<(16384 * 64 + 255) / 256, 256>>>(leaves, Acat0, 16384);

    // l=7: fused GEMM, Acat0 -> Acat1
    {
        dim3 grid(2, 128);
        gemm_fused_l7<<<grid, NTHR, SMEM_TOTAL>>>(
            Acat0, Bcat, vectors + (size_t)offs[7] * D, Acat1, 16384);
    }

    // l=6: split-K S=4 cnt=2, Acat1 -> Acat0
    {
        int M = 4096, S = 4, cnt = 2;
        dim3 grid(2, M / 128, S);
        gemm_partial_kernel<<<grid, NTHR, SMEM_TOTAL>>>(Acat1, Bcat, part, M, cnt);
        int nthr = (M / 4) * 64;
        epilogue_combine_kernel<<<(nthr + 255) / 256, 256>>>(
            part, S, vectors + (size_t)offs[6] * D, Acat0, nullptr, M);
    }

    // l=5: split-K S=8 cnt=1, Acat0 -> Acat1
    {
        int M = 1024, S = 8, cnt = 1;
        dim3 grid(2, M / 128, S);
        gemm_partial_kernel<<<grid, NTHR, SMEM_TOTAL>>>(Acat0, Bcat, part, M, cnt);
        int nthr = (M / 4) * 64;
        epilogue_combine_kernel<<<(nthr + 255) / 256, 256>>>(
            part, S, vectors + (size_t)offs[5] * D, Acat1, nullptr, M);
    }

    // l=4: split-K S=8 cnt=1, Acat1 -> fp32 h (hsA)
    {
        int M = 256, S = 8, cnt = 1;
        dim3 grid(2, M / 128, S);
        gemm_partial_kernel<<<grid, NTHR, SMEM_TOTAL>>>(Acat1, Bcat, part, M, cnt);
        int nthr = (M / 4) * 64;
        epilogue_combine_kernel<<<(nthr + 255) / 256, 256>>>(
            part, S, vectors + (size_t)offs[4] * D, nullptr, hsA, M);
    }

    // l=3..0: fp32 SIMT. hsA -> hsB -> hsA -> hsB -> out
    const float* hin = hsA;
    for (int l = 3; l >= 0; --l) {
        int M = 1 << (2 * l);
        float* hout = (l == 0) ? out : ((l & 1) ? hsB : hsA);
        const float* bias = vectors + (size_t)offs[l] * D;
        int nwarps = M * D;
        small_level_kernel<<<(nwarps * 32 + 255) / 256, 256>>>(hin, Wl, Wr, bias, hout, M);
        hin = hout;
    }
}